// round 4
// baseline (speedup 1.0000x reference)
#include <cuda_runtime.h>

// PMLoss: PoseCNN point-matching loss, single fused kernel.
// Inputs: prediction [B,4C] f32, target [B,4C] f32, weight [B,4C] f32,
// points [C,P,3] f32, symmetry [C] f32. Output: scalar f32.

#define NB        128
#define NC        22
#define NP        1024
#define NPAIR     (NP / 2)
#define NPAD      4                    // prefetch-overrun sentinel entries
#define NCHUNK    8
#define NTHREADS  128                  // == NP / NCHUNK : one p per thread
#define NBLOCKS   (NB * NCHUNK)
#define BIGF      3.402823e38f

#define FXSCALE   1099511627776.0      // 2^40 fixed-point scale

__device__ unsigned long long g_acc;     // zero-init at load; last block resets
__device__ unsigned int       g_count;   // zero-init at load; last block resets

__device__ __forceinline__ unsigned long long pack2(float lo, float hi) {
    unsigned long long r;
    asm("mov.b64 %0, {%1, %2};" : "=l"(r) : "f"(lo), "f"(hi));
    return r;
}
__device__ __forceinline__ void unpack2(unsigned long long v, float& lo, float& hi) {
    asm("mov.b64 {%0, %1}, %2;" : "=f"(lo), "=f"(hi) : "l"(v));
}
// Packed dual fp32 FMA (FFMA2) — only reachable via PTX fma.rn.f32x2.
__device__ __forceinline__ unsigned long long fma2(
    unsigned long long a, unsigned long long b, unsigned long long c) {
    unsigned long long d;
    asm("fma.rn.f32x2 %0, %1, %2, %3;" : "=l"(d) : "l"(a), "l"(b), "l"(c));
    return d;
}

__device__ __forceinline__ float warp_reduce_sum(float v) {
    v += __shfl_xor_sync(0xffffffffu, v, 16);
    v += __shfl_xor_sync(0xffffffffu, v, 8);
    v += __shfl_xor_sync(0xffffffffu, v, 4);
    v += __shfl_xor_sync(0xffffffffu, v, 2);
    v += __shfl_xor_sync(0xffffffffu, v, 1);
    return v;
}

__global__ __launch_bounds__(NTHREADS, 4) void pm_loss_main(
    const float* __restrict__ pred, const float* __restrict__ tgt,
    const float* __restrict__ wgt,  const float* __restrict__ points,
    const float* __restrict__ sym,  float* __restrict__ out)
{
    const int chunk = blockIdx.x;    // consecutive bids = chunks of same ROI
    const int b     = blockIdx.y;    // -> spread heavy ROI across 8 SMs
    const int tid   = threadIdx.x;

    // Packed target-rotated points:
    //   s_xy[i] = { (-2x_{2i}, -2x_{2i+1}), (-2y_{2i}, -2y_{2i+1}) }
    //   s_zw[i] = { (-2z_{2i}, -2z_{2i+1}), ( n_{2i},   n_{2i+1}) }   n = |pt|^2
    __shared__ ulonglong2 s_xy[NPAIR + NPAD];
    __shared__ ulonglong2 s_zw[NPAIR + NPAD];
    __shared__ float  s_R[18];           // Rp[0..8], Rt[9..17]
    __shared__ int    s_cls;
    __shared__ float  s_issym;
    __shared__ float  s_warp[NTHREADS / 32];

    if (tid == 0) {
        // argmax over weight[b, c, 0] (first-max, matching jnp.argmax)
        const float* w = wgt + b * 4 * NC;
        int cls = 0; float best = w[0];
        #pragma unroll
        for (int c = 1; c < NC; c++) {
            float v = w[4 * c];
            if (v > best) { best = v; cls = c; }
        }
        s_cls   = cls;
        s_issym = sym[cls];

        // predicted quaternion (normalized) -> Rp
        const float* qp = pred + b * 4 * NC + 4 * cls;
        float qw = qp[0], qx = qp[1], qy = qp[2], qz = qp[3];
        float inv = rsqrtf(qw*qw + qx*qx + qy*qy + qz*qz);
        qw *= inv; qx *= inv; qy *= inv; qz *= inv;
        s_R[0] = 1.f - 2.f*(qy*qy + qz*qz); s_R[1] = 2.f*(qx*qy - qw*qz); s_R[2] = 2.f*(qx*qz + qw*qy);
        s_R[3] = 2.f*(qx*qy + qw*qz); s_R[4] = 1.f - 2.f*(qx*qx + qz*qz); s_R[5] = 2.f*(qy*qz - qw*qx);
        s_R[6] = 2.f*(qx*qz - qw*qy); s_R[7] = 2.f*(qy*qz + qw*qx); s_R[8] = 1.f - 2.f*(qx*qx + qy*qy);

        // target quaternion (already unit-norm) -> Rt
        const float* qt = tgt + b * 4 * NC + 4 * cls;
        qw = qt[0]; qx = qt[1]; qy = qt[2]; qz = qt[3];
        s_R[ 9] = 1.f - 2.f*(qy*qy + qz*qz); s_R[10] = 2.f*(qx*qy - qw*qz); s_R[11] = 2.f*(qx*qz + qw*qy);
        s_R[12] = 2.f*(qx*qy + qw*qz); s_R[13] = 1.f - 2.f*(qx*qx + qz*qz); s_R[14] = 2.f*(qy*qz - qw*qx);
        s_R[15] = 2.f*(qx*qz - qw*qy); s_R[16] = 2.f*(qy*qz + qw*qx); s_R[17] = 1.f - 2.f*(qx*qx + qy*qy);
    }
    __syncthreads();

    const int cls = s_cls;
    const float* pts = points + (size_t)cls * NP * 3;

    // Rotate all P points by Rt, pack pairs into smem; write sentinels
    {
        const float r0 = s_R[ 9], r1 = s_R[10], r2 = s_R[11];
        const float r3 = s_R[12], r4 = s_R[13], r5 = s_R[14];
        const float r6 = s_R[15], r7 = s_R[16], r8 = s_R[17];
        for (int i = tid; i < NPAIR; i += NTHREADS) {
            int q0 = 2 * i;
            float x0 = pts[3*q0+0], y0 = pts[3*q0+1], z0 = pts[3*q0+2];
            float x1 = pts[3*q0+3], y1 = pts[3*q0+4], z1 = pts[3*q0+5];
            float tx0 = r0*x0 + r1*y0 + r2*z0, tx1 = r0*x1 + r1*y1 + r2*z1;
            float ty0 = r3*x0 + r4*y0 + r5*z0, ty1 = r3*x1 + r4*y1 + r5*z1;
            float tz0 = r6*x0 + r7*y0 + r8*z0, tz1 = r6*x1 + r7*y1 + r8*z1;
            float n0 = tx0*tx0 + ty0*ty0 + tz0*tz0;
            float n1 = tx1*tx1 + ty1*ty1 + tz1*tz1;
            ulonglong2 xy, zw;
            xy.x = pack2(-2.f*tx0, -2.f*tx1);
            xy.y = pack2(-2.f*ty0, -2.f*ty1);
            zw.x = pack2(-2.f*tz0, -2.f*tz1);
            zw.y = pack2(n0, n1);
            s_xy[i] = xy;
            s_zw[i] = zw;
        }
        if (tid < NPAD) {
            ulonglong2 xy, zw;
            xy.x = 0ULL; xy.y = 0ULL; zw.x = 0ULL;
            zw.y = pack2(BIGF, BIGF);            // sentinel: value = BIG, never wins min
            s_xy[NPAIR + tid] = xy;
            s_zw[NPAIR + tid] = zw;
        }
    }
    __syncthreads();

    // This thread's predicted-rotated point
    const int p = chunk * NTHREADS + tid;
    float ppx, ppy, ppz;
    {
        const float r0 = s_R[0], r1 = s_R[1], r2 = s_R[2];
        const float r3 = s_R[3], r4 = s_R[4], r5 = s_R[5];
        const float r6 = s_R[6], r7 = s_R[7], r8 = s_R[8];
        float x = pts[3*p], y = pts[3*p + 1], z = pts[3*p + 2];
        ppx = r0*x + r1*y + r2*z;
        ppy = r3*x + r4*y + r5*z;
        ppz = r6*x + r7*y + r8*z;
    }
    const float cp = ppx*ppx + ppy*ppy + ppz*ppz;

    float acc;
    if (s_issym > 0.f) {
        // |pp - pt_q|^2 = cp + (n_q - 2 pp.pt_q); min over q.
        // Software-pipelined, double-buffered: batch = 4 pair-indices (8 q).
        const unsigned long long px2 = pack2(ppx, ppx);
        const unsigned long long py2 = pack2(ppy, ppy);
        const unsigned long long pz2 = pack2(ppz, ppz);
        float m0 = BIGF, m1 = BIGF, m2 = BIGF, m3 = BIGF;
        float m4 = BIGF, m5 = BIGF, m6 = BIGF, m7 = BIGF;

        ulonglong2 xA0 = s_xy[0], zA0 = s_zw[0];
        ulonglong2 xA1 = s_xy[1], zA1 = s_zw[1];
        ulonglong2 xA2 = s_xy[2], zA2 = s_zw[2];
        ulonglong2 xA3 = s_xy[3], zA3 = s_zw[3];

        #pragma unroll 1
        for (int i = 0; i < NPAIR; i += 4) {
            // prefetch next batch (sentinel-safe overrun on last iteration)
            const int j = i + 4;
            ulonglong2 xB0 = s_xy[j],   zB0 = s_zw[j];
            ulonglong2 xB1 = s_xy[j+1], zB1 = s_zw[j+1];
            ulonglong2 xB2 = s_xy[j+2], zB2 = s_zw[j+2];
            ulonglong2 xB3 = s_xy[j+3], zB3 = s_zw[j+3];

            unsigned long long v0 = fma2(pz2, zA0.x, fma2(py2, xA0.y, fma2(px2, xA0.x, zA0.y)));
            unsigned long long v1 = fma2(pz2, zA1.x, fma2(py2, xA1.y, fma2(px2, xA1.x, zA1.y)));
            unsigned long long v2 = fma2(pz2, zA2.x, fma2(py2, xA2.y, fma2(px2, xA2.x, zA2.y)));
            unsigned long long v3 = fma2(pz2, zA3.x, fma2(py2, xA3.y, fma2(px2, xA3.x, zA3.y)));

            float a0, a1, b0, b1, c0, c1, d0, d1;
            unpack2(v0, a0, a1);
            unpack2(v1, b0, b1);
            unpack2(v2, c0, c1);
            unpack2(v3, d0, d1);
            m0 = fminf(m0, a0); m1 = fminf(m1, a1);
            m2 = fminf(m2, b0); m3 = fminf(m3, b1);
            m4 = fminf(m4, c0); m5 = fminf(m5, c1);
            m6 = fminf(m6, d0); m7 = fminf(m7, d1);

            xA0 = xB0; zA0 = zB0; xA1 = xB1; zA1 = zB1;
            xA2 = xB2; zA2 = zB2; xA3 = xB3; zA3 = zB3;
        }
        acc = cp + fminf(fminf(fminf(m0, m1), fminf(m2, m3)),
                         fminf(fminf(m4, m5), fminf(m6, m7)));
    } else {
        // pointwise |pp_p - pt_p|^2 = cp + (n_p - 2 pp.pt_p) : same expansion at q=p
        int i = p >> 1, lane = p & 1;
        ulonglong2 xy = s_xy[i], zw = s_zw[i];
        float x0, x1, y0, y1, z0, z1, n0, n1;
        unpack2(xy.x, x0, x1);
        unpack2(xy.y, y0, y1);
        unpack2(zw.x, z0, z1);
        unpack2(zw.y, n0, n1);
        float xm = lane ? x1 : x0, ym = lane ? y1 : y0;
        float zm = lane ? z1 : z0, nn = lane ? n1 : n0;
        acc = cp + fmaf(ppx, xm, fmaf(ppy, ym, fmaf(ppz, zm, nn)));
    }

    // Block reduction
    float s = warp_reduce_sum(acc);
    if ((tid & 31) == 0) s_warp[tid >> 5] = s;
    __syncthreads();
    if (tid == 0) {
        float v = s_warp[0];
        #pragma unroll
        for (int wdx = 1; wdx < NTHREADS / 32; wdx++) v += s_warp[wdx];

        // Deterministic fixed-point accumulation (integer adds are associative)
        long long fx = __double2ll_rn((double)v * FXSCALE);
        atomicAdd(&g_acc, (unsigned long long)fx);
        __threadfence();
        unsigned int ticket = atomicAdd(&g_count, 1u);
        if (ticket == NBLOCKS - 1) {
            long long total = (long long)atomicAdd(&g_acc, 0ULL);
            out[0] = (float)((double)total / FXSCALE
                             * (1.0 / (2.0 * (double)NB * (double)NP)));
            // reset for next graph replay (deterministic re-entry)
            g_acc   = 0ULL;
            __threadfence();
            g_count = 0u;
        }
    }
}

extern "C" void kernel_launch(void* const* d_in, const int* in_sizes, int n_in,
                              void* d_out, int out_size) {
    const float* pred = (const float*)d_in[0];
    const float* tgt  = (const float*)d_in[1];
    const float* wgt  = (const float*)d_in[2];
    const float* pts  = (const float*)d_in[3];
    const float* sym  = (const float*)d_in[4];

    dim3 grid(NCHUNK, NB);
    pm_loss_main<<<grid, NTHREADS>>>(pred, tgt, wgt, pts, sym, (float*)d_out);
}

// round 5
// speedup vs baseline: 1.1802x; 1.1802x over previous
#include <cuda_runtime.h>

// PMLoss: PoseCNN point-matching loss, single fused kernel.
// Inputs: prediction [B,4C] f32, target [B,4C] f32, weight [B,4C] f32,
// points [C,P,3] f32, symmetry [C] f32. Output: scalar f32.

#define NB        128
#define NC        22
#define NP        1024
#define NPAIR     (NP / 2)
#define NCHUNK    8
#define NTHREADS  128                  // == NP / NCHUNK : one p per thread
#define NBLOCKS   (NB * NCHUNK)
#define BIGF      3.402823e38f

#define FXSCALE   1099511627776.0      // 2^40 fixed-point scale

__device__ unsigned long long g_acc;     // zero-init at load; last block resets
__device__ unsigned int       g_count;   // zero-init at load; last block resets

__device__ __forceinline__ unsigned long long pack2(float lo, float hi) {
    unsigned long long r;
    asm("mov.b64 %0, {%1, %2};" : "=l"(r) : "f"(lo), "f"(hi));
    return r;
}
__device__ __forceinline__ void unpack2(unsigned long long v, float& lo, float& hi) {
    asm("mov.b64 {%0, %1}, %2;" : "=f"(lo), "=f"(hi) : "l"(v));
}
// Packed dual fp32 FMA (FFMA2) — only reachable via PTX fma.rn.f32x2.
__device__ __forceinline__ unsigned long long fma2(
    unsigned long long a, unsigned long long b, unsigned long long c) {
    unsigned long long d;
    asm("fma.rn.f32x2 %0, %1, %2, %3;" : "=l"(d) : "l"(a), "l"(b), "l"(c));
    return d;
}

__device__ __forceinline__ float warp_reduce_sum(float v) {
    v += __shfl_xor_sync(0xffffffffu, v, 16);
    v += __shfl_xor_sync(0xffffffffu, v, 8);
    v += __shfl_xor_sync(0xffffffffu, v, 4);
    v += __shfl_xor_sync(0xffffffffu, v, 2);
    v += __shfl_xor_sync(0xffffffffu, v, 1);
    return v;
}

__global__ __launch_bounds__(NTHREADS, 4) void pm_loss_main(
    const float* __restrict__ pred, const float* __restrict__ tgt,
    const float* __restrict__ wgt,  const float* __restrict__ points,
    const float* __restrict__ sym,  float* __restrict__ out)
{
    const int chunk = blockIdx.x;    // consecutive bids = chunks of same ROI
    const int b     = blockIdx.y;    // -> spread each ROI across different SMs
    const int tid   = threadIdx.x;

    // Packed target-rotated points (symmetric path only):
    //   s_xy[i] = { (-2x_{2i}, -2x_{2i+1}), (-2y_{2i}, -2y_{2i+1}) }
    //   s_zw[i] = { (-2z_{2i}, -2z_{2i+1}), ( n_{2i},   n_{2i+1}) }   n = |pt|^2
    __shared__ ulonglong2 s_xy[NPAIR];
    __shared__ ulonglong2 s_zw[NPAIR];
    __shared__ float  s_R[18];           // Rp[0..8], Rt[9..17]
    __shared__ int    s_cls;
    __shared__ float  s_issym;
    __shared__ float  s_warp[NTHREADS / 32];

    if (tid == 0) {
        // argmax over weight[b, c, 0] (first-max, matching jnp.argmax)
        const float* w = wgt + b * 4 * NC;
        int cls = 0; float best = w[0];
        #pragma unroll
        for (int c = 1; c < NC; c++) {
            float v = w[4 * c];
            if (v > best) { best = v; cls = c; }
        }
        s_cls   = cls;
        s_issym = sym[cls];

        // predicted quaternion (normalized) -> Rp
        const float* qp = pred + b * 4 * NC + 4 * cls;
        float qw = qp[0], qx = qp[1], qy = qp[2], qz = qp[3];
        float inv = rsqrtf(qw*qw + qx*qx + qy*qy + qz*qz);
        qw *= inv; qx *= inv; qy *= inv; qz *= inv;
        s_R[0] = 1.f - 2.f*(qy*qy + qz*qz); s_R[1] = 2.f*(qx*qy - qw*qz); s_R[2] = 2.f*(qx*qz + qw*qy);
        s_R[3] = 2.f*(qx*qy + qw*qz); s_R[4] = 1.f - 2.f*(qx*qx + qz*qz); s_R[5] = 2.f*(qy*qz - qw*qx);
        s_R[6] = 2.f*(qx*qz - qw*qy); s_R[7] = 2.f*(qy*qz + qw*qx); s_R[8] = 1.f - 2.f*(qx*qx + qy*qy);

        // target quaternion (already unit-norm) -> Rt
        const float* qt = tgt + b * 4 * NC + 4 * cls;
        qw = qt[0]; qx = qt[1]; qy = qt[2]; qz = qt[3];
        s_R[ 9] = 1.f - 2.f*(qy*qy + qz*qz); s_R[10] = 2.f*(qx*qy - qw*qz); s_R[11] = 2.f*(qx*qz + qw*qy);
        s_R[12] = 2.f*(qx*qy + qw*qz); s_R[13] = 1.f - 2.f*(qx*qx + qz*qz); s_R[14] = 2.f*(qy*qz - qw*qx);
        s_R[15] = 2.f*(qx*qz - qw*qy); s_R[16] = 2.f*(qy*qz + qw*qx); s_R[17] = 1.f - 2.f*(qx*qx + qy*qy);
    }
    __syncthreads();

    const int cls   = s_cls;
    const bool symb = (s_issym > 0.f);          // block-uniform
    const float* pts = points + (size_t)cls * NP * 3;

    // This thread's predicted-rotated point
    const int p = chunk * NTHREADS + tid;
    const float px = pts[3*p], py = pts[3*p + 1], pz = pts[3*p + 2];
    float ppx, ppy, ppz;
    {
        const float r0 = s_R[0], r1 = s_R[1], r2 = s_R[2];
        const float r3 = s_R[3], r4 = s_R[4], r5 = s_R[5];
        const float r6 = s_R[6], r7 = s_R[7], r8 = s_R[8];
        ppx = r0*px + r1*py + r2*pz;
        ppy = r3*px + r4*py + r5*pz;
        ppz = r6*px + r7*py + r8*pz;
    }
    const float cp = ppx*ppx + ppy*ppy + ppz*ppz;

    float acc;
    if (symb) {
        // Build target-rotated point table in smem (packed pairs)
        {
            const float r0 = s_R[ 9], r1 = s_R[10], r2 = s_R[11];
            const float r3 = s_R[12], r4 = s_R[13], r5 = s_R[14];
            const float r6 = s_R[15], r7 = s_R[16], r8 = s_R[17];
            for (int i = tid; i < NPAIR; i += NTHREADS) {
                int q0 = 2 * i;
                float x0 = pts[3*q0+0], y0 = pts[3*q0+1], z0 = pts[3*q0+2];
                float x1 = pts[3*q0+3], y1 = pts[3*q0+4], z1 = pts[3*q0+5];
                float tx0 = r0*x0 + r1*y0 + r2*z0, tx1 = r0*x1 + r1*y1 + r2*z1;
                float ty0 = r3*x0 + r4*y0 + r5*z0, ty1 = r3*x1 + r4*y1 + r5*z1;
                float tz0 = r6*x0 + r7*y0 + r8*z0, tz1 = r6*x1 + r7*y1 + r8*z1;
                float n0 = tx0*tx0 + ty0*ty0 + tz0*tz0;
                float n1 = tx1*tx1 + ty1*ty1 + tz1*tz1;
                ulonglong2 xy, zw;
                xy.x = pack2(-2.f*tx0, -2.f*tx1);
                xy.y = pack2(-2.f*ty0, -2.f*ty1);
                zw.x = pack2(-2.f*tz0, -2.f*tz1);
                zw.y = pack2(n0, n1);
                s_xy[i] = xy;
                s_zw[i] = zw;
            }
        }
        __syncthreads();

        // |pp - pt_q|^2 = cp + (n_q - 2 pp.pt_q); min over q.
        // 8 pairs per body: ptxas front-batches the 16 LDS.128 (MLP=16),
        // no cross-iteration register copies.
        const unsigned long long px2 = pack2(ppx, ppx);
        const unsigned long long py2 = pack2(ppy, ppy);
        const unsigned long long pz2 = pack2(ppz, ppz);
        float m0 = BIGF, m1 = BIGF, m2 = BIGF, m3 = BIGF;
        float m4 = BIGF, m5 = BIGF, m6 = BIGF, m7 = BIGF;

        #pragma unroll 1
        for (int i = 0; i < NPAIR; i += 8) {
            ulonglong2 x0 = s_xy[i+0], z0 = s_zw[i+0];
            ulonglong2 x1 = s_xy[i+1], z1 = s_zw[i+1];
            ulonglong2 x2 = s_xy[i+2], z2 = s_zw[i+2];
            ulonglong2 x3 = s_xy[i+3], z3 = s_zw[i+3];
            ulonglong2 x4 = s_xy[i+4], z4 = s_zw[i+4];
            ulonglong2 x5 = s_xy[i+5], z5 = s_zw[i+5];
            ulonglong2 x6 = s_xy[i+6], z6 = s_zw[i+6];
            ulonglong2 x7 = s_xy[i+7], z7 = s_zw[i+7];

            unsigned long long v0 = fma2(pz2, z0.x, fma2(py2, x0.y, fma2(px2, x0.x, z0.y)));
            unsigned long long v1 = fma2(pz2, z1.x, fma2(py2, x1.y, fma2(px2, x1.x, z1.y)));
            unsigned long long v2 = fma2(pz2, z2.x, fma2(py2, x2.y, fma2(px2, x2.x, z2.y)));
            unsigned long long v3 = fma2(pz2, z3.x, fma2(py2, x3.y, fma2(px2, x3.x, z3.y)));
            unsigned long long v4 = fma2(pz2, z4.x, fma2(py2, x4.y, fma2(px2, x4.x, z4.y)));
            unsigned long long v5 = fma2(pz2, z5.x, fma2(py2, x5.y, fma2(px2, x5.x, z5.y)));
            unsigned long long v6 = fma2(pz2, z6.x, fma2(py2, x6.y, fma2(px2, x6.x, z6.y)));
            unsigned long long v7 = fma2(pz2, z7.x, fma2(py2, x7.y, fma2(px2, x7.x, z7.y)));

            float a, bf;
            unpack2(v0, a, bf); m0 = fminf(m0, a); m1 = fminf(m1, bf);
            unpack2(v1, a, bf); m2 = fminf(m2, a); m3 = fminf(m3, bf);
            unpack2(v2, a, bf); m4 = fminf(m4, a); m5 = fminf(m5, bf);
            unpack2(v3, a, bf); m6 = fminf(m6, a); m7 = fminf(m7, bf);
            unpack2(v4, a, bf); m0 = fminf(m0, a); m1 = fminf(m1, bf);
            unpack2(v5, a, bf); m2 = fminf(m2, a); m3 = fminf(m3, bf);
            unpack2(v6, a, bf); m4 = fminf(m4, a); m5 = fminf(m5, bf);
            unpack2(v7, a, bf); m6 = fminf(m6, a); m7 = fminf(m7, bf);
        }
        acc = cp + fminf(fminf(fminf(m0, m1), fminf(m2, m3)),
                         fminf(fminf(m4, m5), fminf(m6, m7)));
    } else {
        // Non-symmetric: rotate own point by Rt directly; |pp - pt|^2.
        const float r0 = s_R[ 9], r1 = s_R[10], r2 = s_R[11];
        const float r3 = s_R[12], r4 = s_R[13], r5 = s_R[14];
        const float r6 = s_R[15], r7 = s_R[16], r8 = s_R[17];
        float tx = r0*px + r1*py + r2*pz;
        float ty = r3*px + r4*py + r5*pz;
        float tz = r6*px + r7*py + r8*pz;
        float dx = ppx - tx, dy = ppy - ty, dz = ppz - tz;
        acc = dx*dx + dy*dy + dz*dz;
        (void)cp;
    }

    // Block reduction
    float s = warp_reduce_sum(acc);
    if ((tid & 31) == 0) s_warp[tid >> 5] = s;
    __syncthreads();
    if (tid == 0) {
        float v = s_warp[0];
        #pragma unroll
        for (int wdx = 1; wdx < NTHREADS / 32; wdx++) v += s_warp[wdx];

        // Deterministic fixed-point accumulation (integer adds are associative)
        long long fx = __double2ll_rn((double)v * FXSCALE);
        atomicAdd(&g_acc, (unsigned long long)fx);
        __threadfence();
        unsigned int ticket = atomicAdd(&g_count, 1u);
        if (ticket == NBLOCKS - 1) {
            long long total = (long long)atomicAdd(&g_acc, 0ULL);
            out[0] = (float)((double)total / FXSCALE
                             * (1.0 / (2.0 * (double)NB * (double)NP)));
            // reset for next graph replay (deterministic re-entry)
            g_acc   = 0ULL;
            __threadfence();
            g_count = 0u;
        }
    }
}

extern "C" void kernel_launch(void* const* d_in, const int* in_sizes, int n_in,
                              void* d_out, int out_size) {
    const float* pred = (const float*)d_in[0];
    const float* tgt  = (const float*)d_in[1];
    const float* wgt  = (const float*)d_in[2];
    const float* pts  = (const float*)d_in[3];
    const float* sym  = (const float*)d_in[4];

    dim3 grid(NCHUNK, NB);
    pm_loss_main<<<grid, NTHREADS>>>(pred, tgt, wgt, pts, sym, (float*)d_out);
}